// round 14
// baseline (speedup 1.0000x reference)
#include <cuda_runtime.h>
#include <cuda_fp16.h>
#include <cstdint>

// FlashAttention B=2,H=16,S=4096,D=64 fp32, non-causal.
// Reference's exact recurrence (block_max variant), BN=128 fixed, in order.
// All-fp16 tensor path, fp32 accumulate; exp2 domain (ex2.approx.f16x2).
// BM=128 with 32 rows/warp (two 16-row groups): each ldmatrix K/V fragment
// feeds 4 MMAs -> smem crossbar traffic per row HALVED vs 16 rows/warp.
// Quarter-wise key processing keeps score regs at 32; packed-P corrected to
// block max via HMUL2 (exact identity when max already global).
// K/V triple-buffered, one __syncthreads per iter; 96KB smem -> 2 CTAs/SM.

#define SEQ   4096
#define HD    64
#define BM    128
#define BN    128
#define NTHR  128
#define NBLK  (SEQ / BN)
#define SCL2E 0.18033688011112042f   // (1/8)*log2(e)
#define ONES2 0x3C003C00u            // half2(1,1)

#define NTOT  (2 * 16 * SEQ * HD)

__device__ __half g_q[NTOT];
__device__ __half g_k[NTOT];
__device__ __half g_v[NTOT];

// ---------------- converter ----------------
__global__ __launch_bounds__(512)
void cvt_kernel(const float* __restrict__ q,
                const float* __restrict__ k,
                const float* __restrict__ v)
{
    int i = blockIdx.x * blockDim.x + threadIdx.x;
    if (i >= NTOT / 4) return;

    float4 tq = ((const float4*)q)[i];
    __half2 qa = __floats2half2_rn(tq.x * SCL2E, tq.y * SCL2E);
    __half2 qb = __floats2half2_rn(tq.z * SCL2E, tq.w * SCL2E);
    *(uint2*)(g_q + 4 * i) = make_uint2(*(uint32_t*)&qa, *(uint32_t*)&qb);

    float4 tk = ((const float4*)k)[i];
    __half2 ka = __floats2half2_rn(tk.x, tk.y);
    __half2 kb = __floats2half2_rn(tk.z, tk.w);
    *(uint2*)(g_k + 4 * i) = make_uint2(*(uint32_t*)&ka, *(uint32_t*)&kb);

    float4 tv = ((const float4*)v)[i];
    __half2 va = __floats2half2_rn(tv.x, tv.y);
    __half2 vb = __floats2half2_rn(tv.z, tv.w);
    *(uint2*)(g_v + 4 * i) = make_uint2(*(uint32_t*)&va, *(uint32_t*)&vb);
}

// ---------------- smem layout (byte offsets) ----------------
// K slots: 0,16384,32768.  V slots: 49152 + (i%3)*16384.
#define O_K0   0
#define O_V0   49152
#define SMEM_BYTES 98304      // 96KB -> 2 CTAs/SM

__device__ __forceinline__ uint32_t swz(uint32_t row, uint32_t ch)
{
    return (row * 8u + (ch ^ (row & 7u))) * 16u;
}

__device__ __forceinline__ void cp16(uint32_t dst, const void* src)
{
    asm volatile("cp.async.cg.shared.global [%0], [%1], 16;" :: "r"(dst), "l"(src));
}
__device__ __forceinline__ void cp_commit() { asm volatile("cp.async.commit_group;"); }
__device__ __forceinline__ void cp_wait1()  { asm volatile("cp.async.wait_group 1;"); }

__device__ __forceinline__ void ldm_x4(uint32_t a, uint32_t* r)
{
    asm volatile("ldmatrix.sync.aligned.m8n8.x4.shared.b16 {%0,%1,%2,%3}, [%4];"
                 : "=r"(r[0]), "=r"(r[1]), "=r"(r[2]), "=r"(r[3]) : "r"(a));
}
__device__ __forceinline__ void ldm_x4t(uint32_t a, uint32_t* r)
{
    asm volatile("ldmatrix.sync.aligned.m8n8.x4.trans.shared.b16 {%0,%1,%2,%3}, [%4];"
                 : "=r"(r[0]), "=r"(r[1]), "=r"(r[2]), "=r"(r[3]) : "r"(a));
}
__device__ __forceinline__ void mma_fp16(float* c, const uint32_t* a,
                                         const uint32_t* b)
{
    asm volatile(
        "mma.sync.aligned.m16n8k16.row.col.f32.f16.f16.f32 "
        "{%0,%1,%2,%3}, {%4,%5,%6,%7}, {%8,%9}, {%0,%1,%2,%3};"
        : "+f"(c[0]), "+f"(c[1]), "+f"(c[2]), "+f"(c[3])
        : "r"(a[0]), "r"(a[1]), "r"(a[2]), "r"(a[3]), "r"(b[0]), "r"(b[1]));
}
__device__ __forceinline__ uint32_t pack2h(float a, float b)
{
    __half2 t = __floats2half2_rn(a, b);
    return *(uint32_t*)&t;
}
__device__ __forceinline__ float ex2f(float x)
{
    float r; asm("ex2.approx.f32 %0, %1;" : "=f"(r) : "f"(x)); return r;
}
__device__ __forceinline__ uint32_t hex2(uint32_t x)
{
    uint32_t r; asm("ex2.approx.f16x2 %0, %1;" : "=r"(r) : "r"(x)); return r;
}
__device__ __forceinline__ uint32_t hmul2u(uint32_t a, uint32_t f)
{
    __half2 r = __hmul2(*(__half2*)&a, *(__half2*)&f);
    return *(uint32_t*)&r;
}

__global__ __launch_bounds__(NTHR, 2)
void fa13_kernel(float* __restrict__ out)
{
    extern __shared__ __align__(16) unsigned char smraw[];
    uint32_t sb = (uint32_t)__cvta_generic_to_shared(smraw);

    const int tid  = threadIdx.x;
    const int lane = tid & 31;
    const int w    = tid >> 5;          // 4 warps; rows 16w..16w+15 and 64+16w..
    const int bh   = blockIdx.y;
    const int qb   = blockIdx.x;

    const size_t kvbase = (size_t)bh * SEQ * HD;

    auto tile_ld = [&](uint32_t dstb, const char* srcb) {
        #pragma unroll
        for (int i = 0; i < 8; i++) {
            int c = tid + i * NTHR;
            cp16(dstb + swz(c >> 3, c & 7),
                 srcb + ((size_t)(c >> 3) * HD + (c & 7) * 8) * 2);
        }
    };
    auto load_K = [&](int i) {
        tile_ld(sb + O_K0 + (i % 3) * 16384,
                (const char*)g_k + (kvbase + (size_t)i * BN * HD) * 2);
    };
    auto load_V = [&](int i) {
        tile_ld(sb + O_V0 + (i % 3) * 16384,
                (const char*)g_v + (kvbase + (size_t)i * BN * HD) * 2);
    };

    // ---- prologue: Q (128x64 = 16KB) staged through V slot 2 ----
    {
        const char* qp = (const char*)(g_q + ((size_t)bh * SEQ + (size_t)qb * BM) * HD);
        #pragma unroll
        for (int i = 0; i < 8; i++) {
            int c = tid + i * NTHR;
            cp16(sb + O_V0 + 2 * 16384 + swz(c >> 3, c & 7),
                 qp + ((size_t)(c >> 3) * HD + (c & 7) * 8) * 2);
        }
    }
    load_K(0); load_V(0);
    cp_commit();                                // g0 = {Q, K0, V0}
    load_K(1); load_V(1);
    cp_commit();                                // g1 = {K1, V1}

    cp_wait1();                                 // g0 done
    __syncthreads();

    // ---- persistent Q fragments for both row-groups ----
    uint32_t qfA[4][4], qfB[4][4];
    {
        int quad = lane >> 3, i = lane & 7;
        int rowA = w * 16 + (quad & 1) * 8 + i;
        #pragma unroll
        for (int t = 0; t < 4; t++) {
            ldm_x4(sb + O_V0 + 2 * 16384 + swz(rowA,      2 * t + (quad >> 1)), qfA[t]);
            ldm_x4(sb + O_V0 + 2 * 16384 + swz(rowA + 64, 2 * t + (quad >> 1)), qfB[t]);
        }
    }

    float oA[8][4], oB[8][4];
    #pragma unroll
    for (int n = 0; n < 8; n++)
        #pragma unroll
        for (int r = 0; r < 4; r++) { oA[n][r] = 0.f; oB[n][r] = 0.f; }
    float osA[4] = {0.f, 0.f, 0.f, 0.f};
    float osB[4] = {0.f, 0.f, 0.f, 0.f};
    float mrA0 = -1e30f, mrA1 = -1e30f, mrB0 = -1e30f, mrB1 = -1e30f;
    const uint32_t bones[2] = {ONES2, ONES2};

    const int rowKB = (lane & 7) + ((lane >> 4) << 3);
    const int chB   = (lane >> 3) & 1;
    const int vri   = lane & 15;
    const int vch   = lane >> 4;

    for (int blk = 0; blk < NBLK; blk++) {
        if (blk) cp_wait1();                    // K/V(blk) arrived
        __syncthreads();                        // + all warps done with blk-1
        // (sync also orders the Q ldmatrix reads before slot-2 overwrite below)

        if (blk + 2 < NBLK) { load_K(blk + 2); load_V(blk + 2); }
        cp_commit();                            // one group per iter, always

        uint32_t kh_b = sb + O_K0 + (blk % 3) * 16384;
        uint32_t vh_b = sb + O_V0 + (blk % 3) * 16384;

        // ---- quarter-wise QK + exp (keys in chunks of 32) ----
        uint32_t ppA[32], ppB[32];
        float qmA0[4], qmA1[4], qmB0[4], qmB1[4];
        #pragma unroll
        for (int qi = 0; qi < 4; qi++) {
            float cA[4][4], cB[4][4];
            #pragma unroll
            for (int j = 0; j < 4; j++)
                #pragma unroll
                for (int r = 0; r < 4; r++) { cA[j][r] = 0.f; cB[j][r] = 0.f; }
            #pragma unroll
            for (int j2 = 0; j2 < 2; j2++) {
                int row = 32 * qi + 16 * j2 + rowKB;
                #pragma unroll
                for (int t = 0; t < 4; t++) {
                    uint32_t b4[4];
                    ldm_x4(kh_b + swz(row, 2 * t + chB), b4);
                    mma_fp16(cA[2*j2],   qfA[t], b4);
                    mma_fp16(cA[2*j2+1], qfA[t], b4 + 2);
                    mma_fp16(cB[2*j2],   qfB[t], b4);
                    mma_fp16(cB[2*j2+1], qfB[t], b4 + 2);
                }
            }
            float a0 = -1e30f, a1 = -1e30f, b0 = -1e30f, b1 = -1e30f;
            #pragma unroll
            for (int j = 0; j < 4; j++) {
                a0 = fmaxf(a0, fmaxf(cA[j][0], cA[j][1]));
                a1 = fmaxf(a1, fmaxf(cA[j][2], cA[j][3]));
                b0 = fmaxf(b0, fmaxf(cB[j][0], cB[j][1]));
                b1 = fmaxf(b1, fmaxf(cB[j][2], cB[j][3]));
            }
            a0 = fmaxf(a0, __shfl_xor_sync(0xffffffffu, a0, 1));
            a0 = fmaxf(a0, __shfl_xor_sync(0xffffffffu, a0, 2));
            a1 = fmaxf(a1, __shfl_xor_sync(0xffffffffu, a1, 1));
            a1 = fmaxf(a1, __shfl_xor_sync(0xffffffffu, a1, 2));
            b0 = fmaxf(b0, __shfl_xor_sync(0xffffffffu, b0, 1));
            b0 = fmaxf(b0, __shfl_xor_sync(0xffffffffu, b0, 2));
            b1 = fmaxf(b1, __shfl_xor_sync(0xffffffffu, b1, 1));
            b1 = fmaxf(b1, __shfl_xor_sync(0xffffffffu, b1, 2));
            qmA0[qi] = a0; qmA1[qi] = a1; qmB0[qi] = b0; qmB1[qi] = b1;
            #pragma unroll
            for (int j = 0; j < 4; j++) {
                ppA[8*qi+2*j]   = hex2(pack2h(cA[j][0] - a0, cA[j][1] - a0));
                ppA[8*qi+2*j+1] = hex2(pack2h(cA[j][2] - a1, cA[j][3] - a1));
                ppB[8*qi+2*j]   = hex2(pack2h(cB[j][0] - b0, cB[j][1] - b0));
                ppB[8*qi+2*j+1] = hex2(pack2h(cB[j][2] - b1, cB[j][3] - b1));
            }
        }

        // ---- block maxes + per-quarter correction to block max ----
        float bmA0 = fmaxf(fmaxf(qmA0[0], qmA0[1]), fmaxf(qmA0[2], qmA0[3]));
        float bmA1 = fmaxf(fmaxf(qmA1[0], qmA1[1]), fmaxf(qmA1[2], qmA1[3]));
        float bmB0 = fmaxf(fmaxf(qmB0[0], qmB0[1]), fmaxf(qmB0[2], qmB0[3]));
        float bmB1 = fmaxf(fmaxf(qmB1[0], qmB1[1]), fmaxf(qmB1[2], qmB1[3]));
        #pragma unroll
        for (int qi = 0; qi < 4; qi++) {
            if (__ballot_sync(0xffffffffu,
                    (qmA0[qi] < bmA0) || (qmA1[qi] < bmA1) ||
                    (qmB0[qi] < bmB0) || (qmB1[qi] < bmB1))) {
                float fa0 = ex2f(qmA0[qi] - bmA0), fa1 = ex2f(qmA1[qi] - bmA1);
                float fb0 = ex2f(qmB0[qi] - bmB0), fb1 = ex2f(qmB1[qi] - bmB1);
                uint32_t uA0 = pack2h(fa0, fa0), uA1 = pack2h(fa1, fa1);
                uint32_t uB0 = pack2h(fb0, fb0), uB1 = pack2h(fb1, fb1);
                #pragma unroll
                for (int j = 0; j < 4; j++) {
                    ppA[8*qi+2*j]   = hmul2u(ppA[8*qi+2*j],   uA0);
                    ppA[8*qi+2*j+1] = hmul2u(ppA[8*qi+2*j+1], uA1);
                    ppB[8*qi+2*j]   = hmul2u(ppB[8*qi+2*j],   uB0);
                    ppB[8*qi+2*j+1] = hmul2u(ppB[8*qi+2*j+1], uB1);
                }
            }
        }

        // ---- rescale O/osum (vote-skip; e==1 exactly when no new max) ----
        if (__ballot_sync(0xffffffffu, (bmA0 > mrA0) || (bmA1 > mrA1) ||
                                       (bmB0 > mrB0) || (bmB1 > mrB1))) {
            float nA0 = fmaxf(mrA0, bmA0), nA1 = fmaxf(mrA1, bmA1);
            float nB0 = fmaxf(mrB0, bmB0), nB1 = fmaxf(mrB1, bmB1);
            float eA0 = ex2f(mrA0 - nA0), eA1 = ex2f(mrA1 - nA1);
            float eB0 = ex2f(mrB0 - nB0), eB1 = ex2f(mrB1 - nB1);
            mrA0 = nA0; mrA1 = nA1; mrB0 = nB0; mrB1 = nB1;
            #pragma unroll
            for (int n = 0; n < 8; n++) {
                oA[n][0] *= eA0; oA[n][1] *= eA0;
                oA[n][2] *= eA1; oA[n][3] *= eA1;
                oB[n][0] *= eB0; oB[n][1] *= eB0;
                oB[n][2] *= eB1; oB[n][3] *= eB1;
            }
            osA[0] *= eA0; osA[1] *= eA0; osA[2] *= eA1; osA[3] *= eA1;
            osB[0] *= eB0; osB[1] *= eB0; osB[2] *= eB1; osB[3] *= eB1;
        }

        // ---- PV: each V fragment feeds 4 MMAs (groups A and B) ----
        #pragma unroll
        for (int t = 0; t < 8; t++) {
            int vrow = 16 * t + vri;
            #pragma unroll
            for (int np = 0; np < 4; np++) {
                uint32_t v4[4];
                ldm_x4t(vh_b + swz(vrow, 2 * np + vch), v4);
                mma_fp16(oA[2*np],   ppA + 4*t, v4);
                mma_fp16(oA[2*np+1], ppA + 4*t, v4 + 2);
                mma_fp16(oB[2*np],   ppB + 4*t, v4);
                mma_fp16(oB[2*np+1], ppB + 4*t, v4 + 2);
            }
            mma_fp16(osA, ppA + 4*t, bones);
            mma_fp16(osB, ppB + 4*t, bones);
        }
    }

    // ---- epilogue ----
    float iA0 = 1.f / (osA[0] + 1e-6f), iA1 = 1.f / (osA[2] + 1e-6f);
    float iB0 = 1.f / (osB[0] + 1e-6f), iB1 = 1.f / (osB[2] + 1e-6f);
    int r  = lane >> 2;
    int cb = (lane & 3) * 2;
    float* ogA0 = out + ((size_t)bh * SEQ + (size_t)qb * BM + w * 16 + r) * HD;
    float* ogA1 = ogA0 + 8 * HD;
    float* ogB0 = ogA0 + 64 * HD;
    float* ogB1 = ogB0 + 8 * HD;
    #pragma unroll
    for (int n = 0; n < 8; n++) {
        *(float2*)(ogA0 + n * 8 + cb) = make_float2(oA[n][0] * iA0, oA[n][1] * iA0);
        *(float2*)(ogA1 + n * 8 + cb) = make_float2(oA[n][2] * iA1, oA[n][3] * iA1);
        *(float2*)(ogB0 + n * 8 + cb) = make_float2(oB[n][0] * iB0, oB[n][1] * iB0);
        *(float2*)(ogB1 + n * 8 + cb) = make_float2(oB[n][2] * iB1, oB[n][3] * iB1);
    }
}

extern "C" void kernel_launch(void* const* d_in, const int* in_sizes, int n_in,
                              void* d_out, int out_size)
{
    const float* q = (const float*)d_in[0];
    const float* k = (const float*)d_in[1];
    const float* v = (const float*)d_in[2];
    float* o = (float*)d_out;

    int n_bh = in_sizes[0] / (SEQ * HD);    // 32

    cudaFuncSetAttribute(fa13_kernel, cudaFuncAttributeMaxDynamicSharedMemorySize,
                         SMEM_BYTES);

    cvt_kernel<<<(NTOT / 4 + 511) / 512, 512>>>(q, k, v);
    dim3 grid(SEQ / BM, n_bh);
    fa13_kernel<<<grid, NTHR, SMEM_BYTES>>>(o);
}